// round 4
// baseline (speedup 1.0000x reference)
#include <cuda_runtime.h>
#include <stdint.h>

#define LSEQ   2048
#define DDIM   64
#define KMAX   64
#define MAXB   16
#define NBUCK  2048         // 2^11 buckets per (batch, group)
#define BSHIFT 21           // bucket = code >> 21 (top 11 bits)
#define CAP    16           // entries per bucket (Poisson(1): P(overflow) ~ 1e-10)

// Static device scratch (no allocation allowed).
__device__ uint32_t           g_qlo[MAXB * LSEQ];
__device__ uint32_t           g_qhi[MAXB * LSEQ];
__device__ int                g_cnt[MAXB * 2 * NBUCK];
__device__ unsigned long long g_ent[(size_t)MAXB * 2 * NBUCK * CAP];

// K1: zero bucket counts for the active batches. int4-vectorized.
__global__ void zero_cnt_kernel(int n4) {
    int i = blockIdx.x * blockDim.x + threadIdx.x;
    if (i < n4) ((int4*)g_cnt)[i] = make_int4(0, 0, 0, 0);
}

// K2: binary-quantize + pack. One warp per token (queries then keys).
// Queries: store packed codes. Keys: scatter (code, index) into hash buckets.
__global__ void pack_scatter_kernel(const float* __restrict__ q,
                                    const float* __restrict__ k,
                                    int ntok) {
    int w    = (blockIdx.x * blockDim.x + threadIdx.x) >> 5;
    int lane = threadIdx.x & 31;
    if (w >= 2 * ntok) return;
    bool is_q = (w < ntok);
    int  t    = is_q ? w : (w - ntok);
    const float* src = is_q ? q : k;

    float a  = src[(size_t)t * DDIM + lane];
    float bb = src[(size_t)t * DDIM + lane + 32];
    uint32_t lo = __ballot_sync(0xFFFFFFFFu, a  > 0.0f);
    uint32_t hi = __ballot_sync(0xFFFFFFFFu, bb > 0.0f);

    if (is_q) {
        if (lane == 0) { g_qlo[t] = lo; g_qhi[t] = hi; }
    } else {
        int b   = t / LSEQ;
        int idx = t - b * LSEQ;                 // key index within batch
        if (lane < 2) {                          // lane0 -> group0, lane1 -> group1
            uint32_t code = lane ? hi : lo;      // ballot results are warp-uniform
            int slot = (b * 2 + lane) * NBUCK + (int)(code >> BSHIFT);
            int p = atomicAdd(&g_cnt[slot], 1);
            if (p < CAP)
                g_ent[(size_t)slot * CAP + p] =
                    ((unsigned long long)code << 32) | (uint32_t)idx;
        }
    }
}

// K3: per-query probe. Each lane owns one query; warp cooperatively fills
// its 32 queries' output (2048 floats) with -1.0 via coalesced float4 stores.
// Rare matches: collect from both group buckets, sort, dedupe, emit ascending.
__global__ void __launch_bounds__(64)
match_kernel(float* __restrict__ out) {
    const int b     = blockIdx.y;
    const int warp  = threadIdx.x >> 5;
    const int lane  = threadIdx.x & 31;
    const int qbase = blockIdx.x * 64 + warp * 32;
    const int qi    = qbase + lane;

    const uint32_t qlo = g_qlo[b * LSEQ + qi];
    const uint32_t qhi = g_qhi[b * LSEQ + qi];

    const int slot0 = (b * 2 + 0) * NBUCK + (int)(qlo >> BSHIFT);
    const int slot1 = (b * 2 + 1) * NBUCK + (int)(qhi >> BSHIFT);
    const int c0 = min(g_cnt[slot0], CAP);
    const int c1 = min(g_cnt[slot1], CAP);

    // Fast count of matches (expected 0).
    int nm = 0;
    for (int e = 0; e < c0; e++) {
        unsigned long long v = g_ent[(size_t)slot0 * CAP + e];
        nm += ((uint32_t)(v >> 32) == qlo);
    }
    for (int e = 0; e < c1; e++) {
        unsigned long long v = g_ent[(size_t)slot1 * CAP + e];
        nm += ((uint32_t)(v >> 32) == qhi);
    }

    // Cooperative -1.0f fill: this warp's 32 queries x 64 floats (8 KB).
    float4* ob = (float4*)(out + ((size_t)b * LSEQ + qbase) * KMAX);
    const float4 neg = make_float4(-1.0f, -1.0f, -1.0f, -1.0f);
    #pragma unroll
    for (int i = 0; i < 16; i++)
        ob[i * 32 + lane] = neg;

    if (__ballot_sync(0xFFFFFFFFu, nm > 0)) {       // warp-uniform, ~never taken
        __syncwarp();                                // order fill before fixups
        if (nm > 0) {
            int list[2 * CAP];
            int n = 0;
            for (int e = 0; e < c0; e++) {
                unsigned long long v = g_ent[(size_t)slot0 * CAP + e];
                if ((uint32_t)(v >> 32) == qlo) list[n++] = (int)(uint32_t)v;
            }
            for (int e = 0; e < c1; e++) {
                unsigned long long v = g_ent[(size_t)slot1 * CAP + e];
                if ((uint32_t)(v >> 32) == qhi) list[n++] = (int)(uint32_t)v;
            }
            // Insertion sort ascending (n <= 32).
            for (int i = 1; i < n; i++) {
                int key = list[i], j = i - 1;
                while (j >= 0 && list[j] > key) { list[j + 1] = list[j]; j--; }
                list[j + 1] = key;
            }
            // Emit unique ascending indices, first KMAX.
            float* o = out + ((size_t)b * LSEQ + qi) * KMAX;
            int pos = 0, prev = -1;
            for (int i = 0; i < n && pos < KMAX; i++) {
                if (list[i] != prev) { o[pos++] = (float)list[i]; prev = list[i]; }
            }
        }
    }
}

extern "C" void kernel_launch(void* const* d_in, const int* in_sizes, int n_in,
                              void* d_out, int out_size) {
    const float* q = (const float*)d_in[0];
    const float* k = (const float*)d_in[1];

    int B = out_size / (LSEQ * KMAX);     // out is [B, L, KMAX] float32
    if (B < 1) B = 1;
    if (B > MAXB) B = MAXB;
    int ntok = B * LSEQ;

    // K1: zero counts (B*2*NBUCK ints, int4-vectorized).
    int n4 = (B * 2 * NBUCK) / 4;
    zero_cnt_kernel<<<(n4 + 255) / 256, 256>>>(n4);

    // K2: pack queries + scatter keys. 2*ntok warps.
    int threads = 256;
    int blocks  = (2 * ntok * 32 + threads - 1) / threads;
    pack_scatter_kernel<<<blocks, threads>>>(q, k, ntok);

    // K3: probe + emit. 64 queries per 64-thread block.
    dim3 grid(LSEQ / 64, B);
    match_kernel<<<grid, 64>>>((float*)d_out);
}